// round 10
// baseline (speedup 1.0000x reference)
#include <cuda_runtime.h>
#include <math.h>

#define NN   20000
#define EE   320000
#define TT   12
#define HH   64
#define CINN 16
#define FF   768      // TT*HH
#define NPB  8        // warps per block

typedef unsigned long long ull;

// ---------------- scratch (static device globals) ---------------------------
__device__ float g_bufA[(size_t)NN * FF];
__device__ float g_bufB[(size_t)NN * FF];
__device__ int   g_cnt[NN];
__device__ int   g_rowptr[NN];
__device__ int   g_fill[NN];
__device__ float g_dinv[NN];
__device__ float g_selfc[NN];
__device__ int2  g_edge[EE];               // (src, coef-as-int)
// fused per-layer weights (12288 floats per layer):
//   region1 (8192 floats): (c*32+ob)*4 + k*2 + comp   for k in {0,1}
//   region2 (4096 floats): 8192 + (c*32+ob)*2 + comp  for k = 2
__device__ float g_M[3 * 12288];
__device__ float g_B[3 * 192];

// ---------------- f32x2 helpers ---------------------------------------------
__device__ __forceinline__ void upk2(ull p, float& lo, float& hi) {
    asm("mov.b64 {%0,%1}, %2;" : "=f"(lo), "=f"(hi) : "l"(p));
}
__device__ __forceinline__ ull fma2(ull a, ull b, ull c) {
    ull d; asm("fma.rn.f32x2 %0,%1,%2,%3;" : "=l"(d) : "l"(a), "l"(b), "l"(c)); return d;
}

// ---------------- graph preprocessing ----------------------------------------
__global__ void k_zero() {
    int i = blockIdx.x * blockDim.x + threadIdx.x;
    if (i < NN) g_cnt[i] = 0;
}

__global__ void k_count(const int* __restrict__ dst) {
    int e = blockIdx.x * blockDim.x + threadIdx.x;
    if (e < EE) atomicAdd(&g_cnt[dst[e]], 1);
}

// single-block: exclusive scan of g_cnt -> g_rowptr, plus dinv/selfc/fill=0
__global__ void k_scan() {
    __shared__ int s[1024];
    int tid = threadIdx.x;
    int base = tid * 20;
    int loc[20], cv[20];
    int tot = 0;
#pragma unroll
    for (int i = 0; i < 20; i++) {
        int idx = base + i;
        int v = (idx < NN) ? g_cnt[idx] : 0;
        cv[i] = v; loc[i] = tot; tot += v;
    }
    s[tid] = tot;
    __syncthreads();
    for (int off = 1; off < 1024; off <<= 1) {
        int v = (tid >= off) ? s[tid - off] : 0;
        __syncthreads();
        s[tid] += v;
        __syncthreads();
    }
    int exc = s[tid] - tot;
#pragma unroll
    for (int i = 0; i < 20; i++) {
        int idx = base + i;
        if (idx < NN) {
            g_rowptr[idx] = exc + loc[i];
            g_fill[idx] = 0;
            float d = (float)(cv[i] + 1);
            g_dinv[idx]  = rsqrtf(d);
            g_selfc[idx] = 1.0f / d;
        }
    }
}

__global__ void k_fill(const int* __restrict__ src, const int* __restrict__ dst) {
    int e = blockIdx.x * blockDim.x + threadIdx.x;
    if (e < EE) {
        int s = src[e], d = dst[e];
        int p = g_rowptr[d] + atomicAdd(&g_fill[d], 1);
        float cf = g_dinv[s] * g_dinv[d];
        g_edge[p] = make_int2(s, __float_as_int(cf));
    }
}

// ---------------- fused-weight precompute ------------------------------------
__global__ __launch_bounds__(256) void k_prep(
    const float* __restrict__ gW, const float* __restrict__ gb,
    const float* __restrict__ cw, const float* __restrict__ cb,
    const float* __restrict__ bng, const float* __restrict__ bnb,
    const float* __restrict__ bnm, const float* __restrict__ bnv)
{
    int l  = blockIdx.x >> 4;
    int bo = blockIdx.x & 15;
    __shared__ float sWt[64 * 65];
    __shared__ float scw4[4 * 192];
    __shared__ float sb[64];
    int tid = threadIdx.x;
    const float* W   = gW + l * 4096;
    const float* cwl = cw + l * 12288;
    for (int i = tid; i < 4096; i += 256) { int c = i >> 6, d = i & 63; sWt[d * 65 + c] = W[i]; }
    for (int i = tid; i < 768; i += 256) scw4[i] = cwl[bo * 768 + i];
    if (tid < 64) sb[tid] = gb[l * 64 + tid];
    __syncthreads();

    int c = tid & 63, ol = tid >> 6;
    int o = bo * 4 + ol;
    float s = bng[l * 64 + o] * rsqrtf(bnv[l * 64 + o] + 1e-5f);
    float h = bnb[l * 64 + o] - bnm[l * 64 + o] * s;

    float m0 = 0.f, m1 = 0.f, m2 = 0.f;
#pragma unroll 4
    for (int d = 0; d < 64; d++) {
        float a = sWt[d * 65 + c];
        const float* wp = scw4 + ol * 192 + d * 3;
        m0 += a * wp[0]; m1 += a * wp[1]; m2 += a * wp[2];
    }
    float* dst = g_M + (size_t)l * 12288;
    int comp = o >> 5, ob = o & 31;
    dst[(c * 32 + ob) * 4 + 0 + comp]    = s * m0;   // k=0 pair
    dst[(c * 32 + ob) * 4 + 2 + comp]    = s * m1;   // k=1 pair
    dst[8192 + (c * 32 + ob) * 2 + comp] = s * m2;   // k=2 pair

    if (c == 0) {
        float b0 = 0.f, b1 = 0.f, b2 = 0.f;
#pragma unroll 4
        for (int d = 0; d < 64; d++) {
            float bd = sb[d];
            const float* wp = scw4 + ol * 192 + d * 3;
            b0 += bd * wp[0]; b1 += bd * wp[1]; b2 += bd * wp[2];
        }
        float cbo = cb[l * 64 + o];
        float Bm  = s * (cbo + b0 + b1 + b2) + h;   // t in [1,10]
        float B0v = s * (cbo + b1 + b2) + h;        // t = 0
        float B11 = s * (cbo + b0 + b1) + h;        // t = 11
        float* db = g_B + l * 192;
        db[(0 * 32 + ob) * 2 + comp] = B0v;
        db[(1 * 32 + ob) * 2 + comp] = Bm;
        db[(2 * 32 + ob) * 2 + comp] = B11;
    }
}

// ---------------- embedding --------------------------------------------------
__global__ __launch_bounds__(256) void k_embed(
    const float* __restrict__ x, const float* __restrict__ We,
    const float* __restrict__ be, float* __restrict__ out)
{
    __shared__ float sWe[CINN * HH];
    __shared__ float sbe[HH];
    __shared__ float sx[NPB][TT * CINN];
    int tid = threadIdx.x, lane = tid & 31, w = tid >> 5;
    for (int i = tid; i < CINN * HH; i += 256) sWe[i] = We[i];
    if (tid < HH) sbe[tid] = be[tid];
    int node = blockIdx.x * NPB + w;
    const float* xr = x + (size_t)node * (TT * CINN);
#pragma unroll
    for (int j = 0; j < 6; j++) sx[w][lane + 32 * j] = xr[lane + 32 * j];
    __syncthreads();
    float* orow = out + (size_t)node * FF;
#pragma unroll
    for (int t = 0; t < TT; t++) {
        float a0 = sbe[lane], a1 = sbe[lane + 32];
#pragma unroll
        for (int c = 0; c < CINN; c++) {
            float xv = sx[w][t * CINN + c];
            a0 += xv * sWe[c * HH + lane];
            a1 += xv * sWe[c * HH + lane + 32];
        }
        orow[t * HH + lane]      = fmaxf(a0, 0.f);
        orow[t * HH + lane + 32] = fmaxf(a1, 0.f);
    }
}

// ---------------- fused ST layer ---------------------------------------------
// phase 1 is done in 3 FEATURE-CHUNK passes over the edge list (256 floats per
// pass). Instantaneous chip-wide L2 footprint per pass = 20000 x 1KB = 20 MB,
// so the ~16x per-row reuse hits L2 instead of thrashing to DRAM.
#define NODES_PER_WARP 2
#define LAYER_SMEM (49152 + 49152)   // weights 48KB + dup agg 48KB

__global__ __launch_bounds__(256, 2) void k_layer(
    const float* __restrict__ xin, float* __restrict__ xout,
    const float* __restrict__ Mp, const float* __restrict__ Bp)
{
    extern __shared__ float sm[];
    ulonglong2* sM01 = (ulonglong2*)sm;            // [c*32+lane] (M0pair,M1pair) 32KB
    ull*        sM2v = ((ull*)sm) + 4096;          // [c*32+lane] M2pair          16KB
    float*      sAd  = sm + 12288;                 // per-warp 1536 floats dup agg

    int tid = threadIdx.x, lane = tid & 31, w = tid >> 5;

    // coalesced staging of fused weights (48 KB)
    {
        const ull* gM64 = (const ull*)Mp;
        ull* sW64 = (ull*)sm;
        for (int i = tid; i < 6144; i += 256) sW64[i] = gM64[i];
    }
    __syncthreads();   // the ONLY block-wide sync

    const ull* gB64 = (const ull*)Bp;
    ull b0v = gB64[lane], bmv = gB64[32 + lane], b11v = gB64[64 + lane];

    float* sA = sAd + w * 1536;
    const float4* xall4 = (const float4*)xin;

#pragma unroll 1
    for (int it = 0; it < NODES_PER_WARP; it++) {
        int node = (blockIdx.x * NPB + w) * NODES_PER_WARP + it;

        // ---- phase 1: CSR gather-aggregate, 3 feature-chunk passes ----
        const float4* xrow4 = xall4 + (size_t)node * 192;
        float4 acc[6];
        float sc = g_selfc[node];
        int rp = g_rowptr[node], ne = g_cnt[node];

#pragma unroll
        for (int p = 0; p < 3; p++) {
            int j0 = 2 * p, j1 = 2 * p + 1;
            float4 a0, a1;
            {
                float4 v0 = xrow4[j0 * 32 + lane];
                float4 v1 = xrow4[j1 * 32 + lane];
                a0 = make_float4(sc * v0.x, sc * v0.y, sc * v0.z, sc * v0.w);
                a1 = make_float4(sc * v1.x, sc * v1.y, sc * v1.z, sc * v1.w);
            }
            int e = 0;
            for (; e + 1 < ne; e += 2) {
                int2 e0 = __ldg(&g_edge[rp + e]);
                int2 e1 = __ldg(&g_edge[rp + e + 1]);
                float c0 = __int_as_float(e0.y), c1 = __int_as_float(e1.y);
                const float4* r0 = xall4 + (size_t)e0.x * 192;
                const float4* r1 = xall4 + (size_t)e1.x * 192;
                float4 u00 = r0[j0 * 32 + lane], u01 = r0[j1 * 32 + lane];
                float4 u10 = r1[j0 * 32 + lane], u11 = r1[j1 * 32 + lane];
                a0.x += c0 * u00.x + c1 * u10.x;  a0.y += c0 * u00.y + c1 * u10.y;
                a0.z += c0 * u00.z + c1 * u10.z;  a0.w += c0 * u00.w + c1 * u10.w;
                a1.x += c0 * u01.x + c1 * u11.x;  a1.y += c0 * u01.y + c1 * u11.y;
                a1.z += c0 * u01.z + c1 * u11.z;  a1.w += c0 * u01.w + c1 * u11.w;
            }
            if (e < ne) {
                int2 e0 = __ldg(&g_edge[rp + e]);
                float c0 = __int_as_float(e0.y);
                const float4* r0 = xall4 + (size_t)e0.x * 192;
                float4 u00 = r0[j0 * 32 + lane], u01 = r0[j1 * 32 + lane];
                a0.x += c0 * u00.x; a0.y += c0 * u00.y; a0.z += c0 * u00.z; a0.w += c0 * u00.w;
                a1.x += c0 * u01.x; a1.y += c0 * u01.y; a1.z += c0 * u01.z; a1.w += c0 * u01.w;
            }
            acc[j0] = a0; acc[j1] = a1;
        }

        __syncwarp();   // prev iteration's readers done before overwrite
        // duplicated store: dup[2f]=dup[2f+1]=flat[f], f = 128j+4lane
#pragma unroll
        for (int j = 0; j < 6; j++) {
            float4 v = acc[j];
            int b4 = 64 * j + 2 * lane;
            ((float4*)sA)[b4]     = make_float4(v.x, v.x, v.y, v.y);
            ((float4*)sA)[b4 + 1] = make_float4(v.z, v.z, v.w, v.w);
        }
        __syncwarp();

        // ---- phase 2: fused GCN+conv+BN, f32x2 over (o0=lane, o1=lane+32) ----
        ull cp[12];
        cp[0] = b0v;
#pragma unroll
        for (int t = 1; t < 11; t++) cp[t] = bmv;
        cp[11] = b11v;

        const ull* sA2 = (const ull*)sA;
#pragma unroll 2
        for (int c = 0; c < 64; c++) {
            ulonglong2 m01 = sM01[c * 32 + lane];
            ull M2 = sM2v[c * 32 + lane];
            const ulonglong2* ad2 = (const ulonglong2*)(sA2 + c * 12);
#pragma unroll
            for (int j = 0; j < 6; j++) {
                ulonglong2 av = ad2[j];
                int t0 = 2 * j, t1 = t0 + 1;
                cp[t0 + 1] = fma2(av.x, m01.x, cp[t0 + 1]);
                cp[t0]     = fma2(av.x, m01.y, cp[t0]);
                if (t0 > 0)  cp[t0 - 1] = fma2(av.x, M2, cp[t0 - 1]);
                if (t1 < 11) cp[t1 + 1] = fma2(av.y, m01.x, cp[t1 + 1]);
                cp[t1]     = fma2(av.y, m01.y, cp[t1]);
                cp[t1 - 1] = fma2(av.y, M2, cp[t1 - 1]);
            }
        }

        // ---- epilogue: residual + relu + store ----
        int d0 = lane, d1 = lane + 32;
        float4* orow4 = (float4*)(xout + (size_t)node * FF);
#pragma unroll
        for (int q = 0; q < 3; q++) {
            float4 r0 = xrow4[d0 * 3 + q];
            float4 r1 = xrow4[d1 * 3 + q];
            float c0a, c1a, c0b, c1b, c0c, c1c, c0d, c1d;
            upk2(cp[q * 4 + 0], c0a, c1a);
            upk2(cp[q * 4 + 1], c0b, c1b);
            upk2(cp[q * 4 + 2], c0c, c1c);
            upk2(cp[q * 4 + 3], c0d, c1d);
            orow4[d0 * 3 + q] = make_float4(
                fmaxf(c0a + r0.x, 0.f), fmaxf(c0b + r0.y, 0.f),
                fmaxf(c0c + r0.z, 0.f), fmaxf(c0d + r0.w, 0.f));
            orow4[d1 * 3 + q] = make_float4(
                fmaxf(c1a + r1.x, 0.f), fmaxf(c1b + r1.y, 0.f),
                fmaxf(c1c + r1.z, 0.f), fmaxf(c1d + r1.w, 0.f));
        }
    }
}

// ---------------- dual attention pooling + output MLP ------------------------
__global__ __launch_bounds__(256) void k_attn(
    const float* __restrict__ xin, float* __restrict__ out,
    const float* __restrict__ taw1, const float* __restrict__ tab1,
    const float* __restrict__ taw2, const float* __restrict__ tab2,
    const float* __restrict__ faw1, const float* __restrict__ fab1,
    const float* __restrict__ faw2, const float* __restrict__ fab2,
    const float* __restrict__ ow1,  const float* __restrict__ ob1,
    const float* __restrict__ ow2,  const float* __restrict__ ob2)
{
    __shared__ float sXa[NPB][FF];
    __shared__ float sTW1[HH * 32];
    __shared__ float sOW1[HH * 32];
    __shared__ float sTB1[32], sTW2[32], sOB1[32], sOW2[32];
    __shared__ float sFW1[TT * 6], sFB1[6], sFW2[6];

    int tid = threadIdx.x, lane = tid & 31, w = tid >> 5;
    for (int i = tid; i < HH * 32; i += 256) { sTW1[i] = taw1[i]; sOW1[i] = ow1[i]; }
    if (tid < 32) { sTB1[tid] = tab1[tid]; sTW2[tid] = taw2[tid];
                    sOB1[tid] = ob1[tid];  sOW2[tid] = ow2[tid]; }
    if (tid < TT * 6) sFW1[tid] = faw1[tid];
    if (tid < 6) { sFB1[tid] = fab1[tid]; sFW2[tid] = faw2[tid]; }

    int node = blockIdx.x * NPB + w;
    const float4* xr4 = (const float4*)(xin + (size_t)node * FF);
#pragma unroll
    for (int j = 0; j < 6; j++) ((float4*)sXa[w])[j * 32 + lane] = xr4[j * 32 + lane];
    __syncthreads();

    float tab2v = tab2[0], fab2v = fab2[0], ob2v = ob2[0];

    float tw[12];
#pragma unroll
    for (int t = 0; t < 12; t++) {
        float m = sTB1[lane];
#pragma unroll
        for (int h = 0; h < 64; h++) m += sXa[w][t * 64 + h] * sTW1[h * 32 + lane];
        m = fmaxf(m, 0.f);
        float c = m * sTW2[lane];
#pragma unroll
        for (int off = 16; off; off >>= 1) c += __shfl_xor_sync(0xffffffffu, c, off);
        tw[t] = c + tab2v;
    }
    float mx = tw[0];
#pragma unroll
    for (int t = 1; t < 12; t++) mx = fmaxf(mx, tw[t]);
    float ssum = 0.f;
#pragma unroll
    for (int t = 0; t < 12; t++) { tw[t] = expf(tw[t] - mx); ssum += tw[t]; }
    float inv = 1.f / ssum;
#pragma unroll
    for (int t = 0; t < 12; t++) tw[t] *= inv;

    float xt0[12], xt1[12];
#pragma unroll
    for (int t = 0; t < 12; t++) {
        xt0[t] = sXa[w][t * 64 + lane]      * tw[t];
        xt1[t] = sXa[w][t * 64 + lane + 32] * tw[t];
    }
    float fs0 = fab2v, fs1 = fab2v;
#pragma unroll
    for (int j = 0; j < 6; j++) {
        float v0 = sFB1[j], v1 = sFB1[j];
#pragma unroll
        for (int t = 0; t < 12; t++) {
            float wv = sFW1[t * 6 + j];
            v0 += xt0[t] * wv;
            v1 += xt1[t] * wv;
        }
        v0 = fmaxf(v0, 0.f); v1 = fmaxf(v1, 0.f);
        float w2 = sFW2[j];
        fs0 += v0 * w2; fs1 += v1 * w2;
    }
    float m2 = fmaxf(fs0, fs1);
#pragma unroll
    for (int off = 16; off; off >>= 1) m2 = fmaxf(m2, __shfl_xor_sync(0xffffffffu, m2, off));
    float e0 = expf(fs0 - m2), e1 = expf(fs1 - m2);
    float es = e0 + e1;
#pragma unroll
    for (int off = 16; off; off >>= 1) es += __shfl_xor_sync(0xffffffffu, es, off);
    float fw0 = e0 / es, fw1 = e1 / es;

    float sum0 = 0.f, sum1 = 0.f;
#pragma unroll
    for (int t = 0; t < 12; t++) { sum0 += xt0[t]; sum1 += xt1[t]; }
    float xf0 = fw0 * sum0, xf1 = fw1 * sum1;

    __syncwarp();
    sXa[w][lane] = xf0; sXa[w][lane + 32] = xf1;
    __syncwarp();

    float y = sOB1[lane];
#pragma unroll
    for (int h = 0; h < 64; h++) y += sXa[w][h] * sOW1[h * 32 + lane];
    y = fmaxf(y, 0.f);
    float c2 = y * sOW2[lane];
#pragma unroll
    for (int off = 16; off; off >>= 1) c2 += __shfl_xor_sync(0xffffffffu, c2, off);
    if (lane == 0) out[node] = c2 + ob2v;
}

// ---------------- launch ------------------------------------------------------
extern "C" void kernel_launch(void* const* d_in, const int* in_sizes, int n_in,
                              void* d_out, int out_size)
{
    const float* x    = (const float*)d_in[0];
    const int*   ei   = (const int*)d_in[1];
    const int*   srcp = ei;
    const int*   dstp = ei + EE;
    const float* We   = (const float*)d_in[2];
    const float* be   = (const float*)d_in[3];
    const float* gW   = (const float*)d_in[4];
    const float* gb   = (const float*)d_in[5];
    const float* cw   = (const float*)d_in[6];
    const float* cb   = (const float*)d_in[7];
    const float* bng  = (const float*)d_in[8];
    const float* bnb  = (const float*)d_in[9];
    const float* bnm  = (const float*)d_in[10];
    const float* bnv  = (const float*)d_in[11];
    const float* taw1 = (const float*)d_in[12];
    const float* tab1 = (const float*)d_in[13];
    const float* taw2 = (const float*)d_in[14];
    const float* tab2 = (const float*)d_in[15];
    const float* faw1 = (const float*)d_in[16];
    const float* fab1 = (const float*)d_in[17];
    const float* faw2 = (const float*)d_in[18];
    const float* fab2 = (const float*)d_in[19];
    const float* ow1  = (const float*)d_in[20];
    const float* ob1  = (const float*)d_in[21];
    const float* ow2  = (const float*)d_in[22];
    const float* ob2  = (const float*)d_in[23];
    float* out = (float*)d_out;

    cudaFuncSetAttribute(k_layer, cudaFuncAttributeMaxDynamicSharedMemorySize, LAYER_SMEM);

    void *pA = nullptr, *pB = nullptr, *pM = nullptr, *pBi = nullptr;
    cudaGetSymbolAddress(&pA, g_bufA);
    cudaGetSymbolAddress(&pB, g_bufB);
    cudaGetSymbolAddress(&pM, g_M);
    cudaGetSymbolAddress(&pBi, g_B);
    float* bufA = (float*)pA;
    float* bufB = (float*)pB;
    const float* Mb = (const float*)pM;
    const float* Bb = (const float*)pBi;

    k_zero <<<(NN + 255) / 256, 256>>>();
    k_count<<<(EE + 255) / 256, 256>>>(dstp);
    k_scan <<<1, 1024>>>();
    k_fill <<<(EE + 255) / 256, 256>>>(srcp, dstp);
    k_prep <<<48, 256>>>(gW, gb, cw, cb, bng, bnb, bnm, bnv);

    k_embed<<<NN / NPB, 256>>>(x, We, be, bufA);

    int lgrid = NN / (NPB * NODES_PER_WARP);   // 1250
    k_layer<<<lgrid, 256, LAYER_SMEM>>>(bufA, bufB, Mb + 0 * 12288, Bb + 0 * 192);
    k_layer<<<lgrid, 256, LAYER_SMEM>>>(bufB, bufA, Mb + 1 * 12288, Bb + 1 * 192);
    k_layer<<<lgrid, 256, LAYER_SMEM>>>(bufA, bufB, Mb + 2 * 12288, Bb + 2 * 192);

    k_attn<<<NN / NPB, 256>>>(bufB, out,
        taw1, tab1, taw2, tab2, faw1, fab1, faw2, fab2,
        ow1, ob1, ow2, ob2);
}

// round 11
// speedup vs baseline: 1.0719x; 1.0719x over previous
#include <cuda_runtime.h>
#include <cuda_fp16.h>
#include <math.h>

#define NN   20000
#define EE   320000
#define TT   12
#define HH   64
#define CINN 16
#define FF   768      // TT*HH
#define NPB  8        // warps per block

typedef unsigned long long ull;

// ---------------- scratch (static device globals) ---------------------------
__device__ __half g_bufA[(size_t)NN * FF];   // fp16 activations (ping)
__device__ __half g_bufB[(size_t)NN * FF];   // fp16 activations (pong)
__device__ int   g_cnt[NN];
__device__ int   g_rowptr[NN];
__device__ int   g_fill[NN];
__device__ float g_dinv[NN];
__device__ float g_selfc[NN];
__device__ int2  g_edge[EE];                 // (src, coef-as-int)
// fused per-layer weights (12288 floats per layer):
//   region1 (8192 floats): (c*32+ob)*4 + k*2 + comp   for k in {0,1}
//   region2 (4096 floats): 8192 + (c*32+ob)*2 + comp  for k = 2
__device__ float g_M[3 * 12288];
__device__ float g_B[3 * 192];

// ---------------- f32x2 helpers ---------------------------------------------
__device__ __forceinline__ void upk2(ull p, float& lo, float& hi) {
    asm("mov.b64 {%0,%1}, %2;" : "=f"(lo), "=f"(hi) : "l"(p));
}
__device__ __forceinline__ ull fma2(ull a, ull b, ull c) {
    ull d; asm("fma.rn.f32x2 %0,%1,%2,%3;" : "=l"(d) : "l"(a), "l"(b), "l"(c)); return d;
}
// 4 halves in a uint2 -> float4
__device__ __forceinline__ float4 h4_to_f4(uint2 u) {
    half2 ha = *reinterpret_cast<const half2*>(&u.x);
    half2 hb = *reinterpret_cast<const half2*>(&u.y);
    float2 fa = __half22float2(ha), fb = __half22float2(hb);
    return make_float4(fa.x, fa.y, fb.x, fb.y);
}
__device__ __forceinline__ uint2 f4_to_h4(float4 v) {
    half2 ha = __floats2half2_rn(v.x, v.y);
    half2 hb = __floats2half2_rn(v.z, v.w);
    uint2 u;
    u.x = *reinterpret_cast<const unsigned int*>(&ha);
    u.y = *reinterpret_cast<const unsigned int*>(&hb);
    return u;
}

// ---------------- graph preprocessing ----------------------------------------
__global__ void k_zero() {
    int i = blockIdx.x * blockDim.x + threadIdx.x;
    if (i < NN) g_cnt[i] = 0;
}

__global__ void k_count(const int* __restrict__ dst) {
    int e = blockIdx.x * blockDim.x + threadIdx.x;
    if (e < EE) atomicAdd(&g_cnt[dst[e]], 1);
}

// single-block: exclusive scan of g_cnt -> g_rowptr, plus dinv/selfc/fill=0
__global__ void k_scan() {
    __shared__ int s[1024];
    int tid = threadIdx.x;
    int base = tid * 20;
    int loc[20], cv[20];
    int tot = 0;
#pragma unroll
    for (int i = 0; i < 20; i++) {
        int idx = base + i;
        int v = (idx < NN) ? g_cnt[idx] : 0;
        cv[i] = v; loc[i] = tot; tot += v;
    }
    s[tid] = tot;
    __syncthreads();
    for (int off = 1; off < 1024; off <<= 1) {
        int v = (tid >= off) ? s[tid - off] : 0;
        __syncthreads();
        s[tid] += v;
        __syncthreads();
    }
    int exc = s[tid] - tot;
#pragma unroll
    for (int i = 0; i < 20; i++) {
        int idx = base + i;
        if (idx < NN) {
            g_rowptr[idx] = exc + loc[i];
            g_fill[idx] = 0;
            float d = (float)(cv[i] + 1);
            g_dinv[idx]  = rsqrtf(d);
            g_selfc[idx] = 1.0f / d;
        }
    }
}

__global__ void k_fill(const int* __restrict__ src, const int* __restrict__ dst) {
    int e = blockIdx.x * blockDim.x + threadIdx.x;
    if (e < EE) {
        int s = src[e], d = dst[e];
        int p = g_rowptr[d] + atomicAdd(&g_fill[d], 1);
        float cf = g_dinv[s] * g_dinv[d];
        g_edge[p] = make_int2(s, __float_as_int(cf));
    }
}

// ---------------- fused-weight precompute ------------------------------------
__global__ __launch_bounds__(256) void k_prep(
    const float* __restrict__ gW, const float* __restrict__ gb,
    const float* __restrict__ cw, const float* __restrict__ cb,
    const float* __restrict__ bng, const float* __restrict__ bnb,
    const float* __restrict__ bnm, const float* __restrict__ bnv)
{
    int l  = blockIdx.x >> 4;
    int bo = blockIdx.x & 15;
    __shared__ float sWt[64 * 65];
    __shared__ float scw4[4 * 192];
    __shared__ float sb[64];
    int tid = threadIdx.x;
    const float* W   = gW + l * 4096;
    const float* cwl = cw + l * 12288;
    for (int i = tid; i < 4096; i += 256) { int c = i >> 6, d = i & 63; sWt[d * 65 + c] = W[i]; }
    for (int i = tid; i < 768; i += 256) scw4[i] = cwl[bo * 768 + i];
    if (tid < 64) sb[tid] = gb[l * 64 + tid];
    __syncthreads();

    int c = tid & 63, ol = tid >> 6;
    int o = bo * 4 + ol;
    float s = bng[l * 64 + o] * rsqrtf(bnv[l * 64 + o] + 1e-5f);
    float h = bnb[l * 64 + o] - bnm[l * 64 + o] * s;

    float m0 = 0.f, m1 = 0.f, m2 = 0.f;
#pragma unroll 4
    for (int d = 0; d < 64; d++) {
        float a = sWt[d * 65 + c];
        const float* wp = scw4 + ol * 192 + d * 3;
        m0 += a * wp[0]; m1 += a * wp[1]; m2 += a * wp[2];
    }
    float* dst = g_M + (size_t)l * 12288;
    int comp = o >> 5, ob = o & 31;
    dst[(c * 32 + ob) * 4 + 0 + comp]    = s * m0;   // k=0 pair
    dst[(c * 32 + ob) * 4 + 2 + comp]    = s * m1;   // k=1 pair
    dst[8192 + (c * 32 + ob) * 2 + comp] = s * m2;   // k=2 pair

    if (c == 0) {
        float b0 = 0.f, b1 = 0.f, b2 = 0.f;
#pragma unroll 4
        for (int d = 0; d < 64; d++) {
            float bd = sb[d];
            const float* wp = scw4 + ol * 192 + d * 3;
            b0 += bd * wp[0]; b1 += bd * wp[1]; b2 += bd * wp[2];
        }
        float cbo = cb[l * 64 + o];
        float Bm  = s * (cbo + b0 + b1 + b2) + h;   // t in [1,10]
        float B0v = s * (cbo + b1 + b2) + h;        // t = 0
        float B11 = s * (cbo + b0 + b1) + h;        // t = 11
        float* db = g_B + l * 192;
        db[(0 * 32 + ob) * 2 + comp] = B0v;
        db[(1 * 32 + ob) * 2 + comp] = Bm;
        db[(2 * 32 + ob) * 2 + comp] = B11;
    }
}

// ---------------- embedding (writes fp16) ------------------------------------
__global__ __launch_bounds__(256) void k_embed(
    const float* __restrict__ x, const float* __restrict__ We,
    const float* __restrict__ be, __half* __restrict__ out)
{
    __shared__ float sWe[CINN * HH];
    __shared__ float sbe[HH];
    __shared__ float sx[NPB][TT * CINN];
    int tid = threadIdx.x, lane = tid & 31, w = tid >> 5;
    for (int i = tid; i < CINN * HH; i += 256) sWe[i] = We[i];
    if (tid < HH) sbe[tid] = be[tid];
    int node = blockIdx.x * NPB + w;
    const float* xr = x + (size_t)node * (TT * CINN);
#pragma unroll
    for (int j = 0; j < 6; j++) sx[w][lane + 32 * j] = xr[lane + 32 * j];
    __syncthreads();
    __half* orow = out + (size_t)node * FF;
#pragma unroll
    for (int t = 0; t < TT; t++) {
        float a0 = sbe[lane], a1 = sbe[lane + 32];
#pragma unroll
        for (int c = 0; c < CINN; c++) {
            float xv = sx[w][t * CINN + c];
            a0 += xv * sWe[c * HH + lane];
            a1 += xv * sWe[c * HH + lane + 32];
        }
        orow[t * HH + lane]      = __float2half_rn(fmaxf(a0, 0.f));
        orow[t * HH + lane + 32] = __float2half_rn(fmaxf(a1, 0.f));
    }
}

// ---------------- fused ST layer (fp16 activations, fp32 math) ---------------
#define NODES_PER_WARP 2
#define LAYER_SMEM (49152 + 49152)   // weights 48KB + dup agg 48KB

__global__ __launch_bounds__(256, 2) void k_layer(
    const __half* __restrict__ xin, __half* __restrict__ xout,
    const float* __restrict__ Mp, const float* __restrict__ Bp)
{
    extern __shared__ float sm[];
    ulonglong2* sM01 = (ulonglong2*)sm;            // [c*32+lane] (M0pair,M1pair) 32KB
    ull*        sM2v = ((ull*)sm) + 4096;          // [c*32+lane] M2pair          16KB
    float*      sAd  = sm + 12288;                 // per-warp 1536 floats dup agg

    int tid = threadIdx.x, lane = tid & 31, w = tid >> 5;

    // coalesced staging of fused weights (48 KB)
    {
        const ull* gM64 = (const ull*)Mp;
        ull* sW64 = (ull*)sm;
        for (int i = tid; i < 6144; i += 256) sW64[i] = gM64[i];
    }
    __syncthreads();   // the ONLY block-wide sync

    const ull* gB64 = (const ull*)Bp;
    ull b0v = gB64[lane], bmv = gB64[32 + lane], b11v = gB64[64 + lane];

    float* sA = sAd + w * 1536;
    const uint2* xall = (const uint2*)xin;         // row = 192 uint2 (768 halves)

#pragma unroll 1
    for (int it = 0; it < NODES_PER_WARP; it++) {
        int node = (blockIdx.x * NPB + w) * NODES_PER_WARP + it;

        // ---- phase 1: CSR gather-aggregate (fp16 rows -> fp32 acc) ----
        const uint2* xrow = xall + (size_t)node * 192;
        float4 acc[6];
        float sc = g_selfc[node];
#pragma unroll
        for (int j = 0; j < 6; j++) {
            float4 v = h4_to_f4(xrow[j * 32 + lane]);
            acc[j] = make_float4(sc * v.x, sc * v.y, sc * v.z, sc * v.w);
        }
        int rp = g_rowptr[node], ne = g_cnt[node];
        int e = 0;
        for (; e + 1 < ne; e += 2) {
            int2 e0 = __ldg(&g_edge[rp + e]);
            int2 e1 = __ldg(&g_edge[rp + e + 1]);
            float c0 = __int_as_float(e0.y), c1 = __int_as_float(e1.y);
            const uint2* r0 = xall + (size_t)e0.x * 192;
            const uint2* r1 = xall + (size_t)e1.x * 192;
            uint2 u0[6], u1[6];
#pragma unroll
            for (int j = 0; j < 6; j++) { u0[j] = r0[j * 32 + lane]; u1[j] = r1[j * 32 + lane]; }
#pragma unroll
            for (int j = 0; j < 6; j++) {
                float4 v0 = h4_to_f4(u0[j]);
                float4 v1 = h4_to_f4(u1[j]);
                acc[j].x += c0 * v0.x + c1 * v1.x;
                acc[j].y += c0 * v0.y + c1 * v1.y;
                acc[j].z += c0 * v0.z + c1 * v1.z;
                acc[j].w += c0 * v0.w + c1 * v1.w;
            }
        }
        if (e < ne) {
            int2 e0 = __ldg(&g_edge[rp + e]);
            float c0 = __int_as_float(e0.y);
            const uint2* r0 = xall + (size_t)e0.x * 192;
#pragma unroll
            for (int j = 0; j < 6; j++) {
                float4 v = h4_to_f4(r0[j * 32 + lane]);
                acc[j].x += c0 * v.x; acc[j].y += c0 * v.y;
                acc[j].z += c0 * v.z; acc[j].w += c0 * v.w;
            }
        }
        __syncwarp();   // prev iteration's readers done before overwrite
        // duplicated store: dup[2f]=dup[2f+1]=flat[f], f = 128j+4lane
#pragma unroll
        for (int j = 0; j < 6; j++) {
            float4 v = acc[j];
            int b4 = 64 * j + 2 * lane;
            ((float4*)sA)[b4]     = make_float4(v.x, v.x, v.y, v.y);
            ((float4*)sA)[b4 + 1] = make_float4(v.z, v.z, v.w, v.w);
        }
        __syncwarp();

        // ---- phase 2: fused GCN+conv+BN, f32x2 over (o0=lane, o1=lane+32) ----
        ull cp[12];
        cp[0] = b0v;
#pragma unroll
        for (int t = 1; t < 11; t++) cp[t] = bmv;
        cp[11] = b11v;

        const ull* sA2 = (const ull*)sA;
#pragma unroll 2
        for (int c = 0; c < 64; c++) {
            ulonglong2 m01 = sM01[c * 32 + lane];
            ull M2 = sM2v[c * 32 + lane];
            const ulonglong2* ad2 = (const ulonglong2*)(sA2 + c * 12);
#pragma unroll
            for (int j = 0; j < 6; j++) {
                ulonglong2 av = ad2[j];
                int t0 = 2 * j, t1 = t0 + 1;
                cp[t0 + 1] = fma2(av.x, m01.x, cp[t0 + 1]);
                cp[t0]     = fma2(av.x, m01.y, cp[t0]);
                if (t0 > 0)  cp[t0 - 1] = fma2(av.x, M2, cp[t0 - 1]);
                if (t1 < 11) cp[t1 + 1] = fma2(av.y, m01.x, cp[t1 + 1]);
                cp[t1]     = fma2(av.y, m01.y, cp[t1]);
                cp[t1 - 1] = fma2(av.y, M2, cp[t1 - 1]);
            }
        }

        // ---- epilogue: residual (fp16) + relu + store (fp16) ----
        int d0 = lane, d1 = lane + 32;
        uint2* orow = (uint2*)(xout + (size_t)node * FF);
#pragma unroll
        for (int q = 0; q < 3; q++) {
            float4 r0 = h4_to_f4(xrow[d0 * 3 + q]);
            float4 r1 = h4_to_f4(xrow[d1 * 3 + q]);
            float c0a, c1a, c0b, c1b, c0c, c1c, c0d, c1d;
            upk2(cp[q * 4 + 0], c0a, c1a);
            upk2(cp[q * 4 + 1], c0b, c1b);
            upk2(cp[q * 4 + 2], c0c, c1c);
            upk2(cp[q * 4 + 3], c0d, c1d);
            float4 o0v = make_float4(
                fmaxf(c0a + r0.x, 0.f), fmaxf(c0b + r0.y, 0.f),
                fmaxf(c0c + r0.z, 0.f), fmaxf(c0d + r0.w, 0.f));
            float4 o1v = make_float4(
                fmaxf(c1a + r1.x, 0.f), fmaxf(c1b + r1.y, 0.f),
                fmaxf(c1c + r1.z, 0.f), fmaxf(c1d + r1.w, 0.f));
            orow[d0 * 3 + q] = f4_to_h4(o0v);
            orow[d1 * 3 + q] = f4_to_h4(o1v);
        }
    }
}

// ---------------- dual attention pooling + output MLP (reads fp16) -----------
__global__ __launch_bounds__(256) void k_attn(
    const __half* __restrict__ xin, float* __restrict__ out,
    const float* __restrict__ taw1, const float* __restrict__ tab1,
    const float* __restrict__ taw2, const float* __restrict__ tab2,
    const float* __restrict__ faw1, const float* __restrict__ fab1,
    const float* __restrict__ faw2, const float* __restrict__ fab2,
    const float* __restrict__ ow1,  const float* __restrict__ ob1,
    const float* __restrict__ ow2,  const float* __restrict__ ob2)
{
    __shared__ float sXa[NPB][FF];
    __shared__ float sTW1[HH * 32];
    __shared__ float sOW1[HH * 32];
    __shared__ float sTB1[32], sTW2[32], sOB1[32], sOW2[32];
    __shared__ float sFW1[TT * 6], sFB1[6], sFW2[6];

    int tid = threadIdx.x, lane = tid & 31, w = tid >> 5;
    for (int i = tid; i < HH * 32; i += 256) { sTW1[i] = taw1[i]; sOW1[i] = ow1[i]; }
    if (tid < 32) { sTB1[tid] = tab1[tid]; sTW2[tid] = taw2[tid];
                    sOB1[tid] = ob1[tid];  sOW2[tid] = ow2[tid]; }
    if (tid < TT * 6) sFW1[tid] = faw1[tid];
    if (tid < 6) { sFB1[tid] = fab1[tid]; sFW2[tid] = faw2[tid]; }

    int node = blockIdx.x * NPB + w;
    const uint2* xr = (const uint2*)(xin + (size_t)node * FF);
#pragma unroll
    for (int j = 0; j < 6; j++)
        ((float4*)sXa[w])[j * 32 + lane] = h4_to_f4(xr[j * 32 + lane]);
    __syncthreads();

    float tab2v = tab2[0], fab2v = fab2[0], ob2v = ob2[0];

    float tw[12];
#pragma unroll
    for (int t = 0; t < 12; t++) {
        float m = sTB1[lane];
#pragma unroll
        for (int h = 0; h < 64; h++) m += sXa[w][t * 64 + h] * sTW1[h * 32 + lane];
        m = fmaxf(m, 0.f);
        float c = m * sTW2[lane];
#pragma unroll
        for (int off = 16; off; off >>= 1) c += __shfl_xor_sync(0xffffffffu, c, off);
        tw[t] = c + tab2v;
    }
    float mx = tw[0];
#pragma unroll
    for (int t = 1; t < 12; t++) mx = fmaxf(mx, tw[t]);
    float ssum = 0.f;
#pragma unroll
    for (int t = 0; t < 12; t++) { tw[t] = expf(tw[t] - mx); ssum += tw[t]; }
    float inv = 1.f / ssum;
#pragma unroll
    for (int t = 0; t < 12; t++) tw[t] *= inv;

    float xt0[12], xt1[12];
#pragma unroll
    for (int t = 0; t < 12; t++) {
        xt0[t] = sXa[w][t * 64 + lane]      * tw[t];
        xt1[t] = sXa[w][t * 64 + lane + 32] * tw[t];
    }
    float fs0 = fab2v, fs1 = fab2v;
#pragma unroll
    for (int j = 0; j < 6; j++) {
        float v0 = sFB1[j], v1 = sFB1[j];
#pragma unroll
        for (int t = 0; t < 12; t++) {
            float wv = sFW1[t * 6 + j];
            v0 += xt0[t] * wv;
            v1 += xt1[t] * wv;
        }
        v0 = fmaxf(v0, 0.f); v1 = fmaxf(v1, 0.f);
        float w2 = sFW2[j];
        fs0 += v0 * w2; fs1 += v1 * w2;
    }
    float m2 = fmaxf(fs0, fs1);
#pragma unroll
    for (int off = 16; off; off >>= 1) m2 = fmaxf(m2, __shfl_xor_sync(0xffffffffu, m2, off));
    float e0 = expf(fs0 - m2), e1 = expf(fs1 - m2);
    float es = e0 + e1;
#pragma unroll
    for (int off = 16; off; off >>= 1) es += __shfl_xor_sync(0xffffffffu, es, off);
    float fw0 = e0 / es, fw1 = e1 / es;

    float sum0 = 0.f, sum1 = 0.f;
#pragma unroll
    for (int t = 0; t < 12; t++) { sum0 += xt0[t]; sum1 += xt1[t]; }
    float xf0 = fw0 * sum0, xf1 = fw1 * sum1;

    __syncwarp();
    sXa[w][lane] = xf0; sXa[w][lane + 32] = xf1;
    __syncwarp();

    float y = sOB1[lane];
#pragma unroll
    for (int h = 0; h < 64; h++) y += sXa[w][h] * sOW1[h * 32 + lane];
    y = fmaxf(y, 0.f);
    float c2 = y * sOW2[lane];
#pragma unroll
    for (int off = 16; off; off >>= 1) c2 += __shfl_xor_sync(0xffffffffu, c2, off);
    if (lane == 0) out[node] = c2 + ob2v;
}

// ---------------- launch ------------------------------------------------------
extern "C" void kernel_launch(void* const* d_in, const int* in_sizes, int n_in,
                              void* d_out, int out_size)
{
    const float* x    = (const float*)d_in[0];
    const int*   ei   = (const int*)d_in[1];
    const int*   srcp = ei;
    const int*   dstp = ei + EE;
    const float* We   = (const float*)d_in[2];
    const float* be   = (const float*)d_in[3];
    const float* gW   = (const float*)d_in[4];
    const float* gb   = (const float*)d_in[5];
    const float* cw   = (const float*)d_in[6];
    const float* cb   = (const float*)d_in[7];
    const float* bng  = (const float*)d_in[8];
    const float* bnb  = (const float*)d_in[9];
    const float* bnm  = (const float*)d_in[10];
    const float* bnv  = (const float*)d_in[11];
    const float* taw1 = (const float*)d_in[12];
    const float* tab1 = (const float*)d_in[13];
    const float* taw2 = (const float*)d_in[14];
    const float* tab2 = (const float*)d_in[15];
    const float* faw1 = (const float*)d_in[16];
    const float* fab1 = (const float*)d_in[17];
    const float* faw2 = (const float*)d_in[18];
    const float* fab2 = (const float*)d_in[19];
    const float* ow1  = (const float*)d_in[20];
    const float* ob1  = (const float*)d_in[21];
    const float* ow2  = (const float*)d_in[22];
    const float* ob2  = (const float*)d_in[23];
    float* out = (float*)d_out;

    cudaFuncSetAttribute(k_layer, cudaFuncAttributeMaxDynamicSharedMemorySize, LAYER_SMEM);

    void *pA = nullptr, *pB = nullptr, *pM = nullptr, *pBi = nullptr;
    cudaGetSymbolAddress(&pA, g_bufA);
    cudaGetSymbolAddress(&pB, g_bufB);
    cudaGetSymbolAddress(&pM, g_M);
    cudaGetSymbolAddress(&pBi, g_B);
    __half* bufA = (__half*)pA;
    __half* bufB = (__half*)pB;
    const float* Mb = (const float*)pM;
    const float* Bb = (const float*)pBi;

    k_zero <<<(NN + 255) / 256, 256>>>();
    k_count<<<(EE + 255) / 256, 256>>>(dstp);
    k_scan <<<1, 1024>>>();
    k_fill <<<(EE + 255) / 256, 256>>>(srcp, dstp);
    k_prep <<<48, 256>>>(gW, gb, cw, cb, bng, bnb, bnm, bnv);

    k_embed<<<NN / NPB, 256>>>(x, We, be, bufA);

    int lgrid = NN / (NPB * NODES_PER_WARP);   // 1250
    k_layer<<<lgrid, 256, LAYER_SMEM>>>(bufA, bufB, Mb + 0 * 12288, Bb + 0 * 192);
    k_layer<<<lgrid, 256, LAYER_SMEM>>>(bufB, bufA, Mb + 1 * 12288, Bb + 1 * 192);
    k_layer<<<lgrid, 256, LAYER_SMEM>>>(bufA, bufB, Mb + 2 * 12288, Bb + 2 * 192);

    k_attn<<<NN / NPB, 256>>>(bufB, out,
        taw1, tab1, taw2, tab2, faw1, fab1, faw2, fab2,
        ow1, ob1, ow2, ob2);
}